// round 8
// baseline (speedup 1.0000x reference)
#include <cuda_runtime.h>
#include <math.h>

#define FULL 0xFFFFFFFFu
#define T_LEN 2048
#define CHUNKS 16          // 16 chunks x 128 elems = 2048
#define WPB 8              // warps per block

__global__ __launch_bounds__(256, 6)
void scpp_kernel(const float* __restrict__ event_times,
                 const float* __restrict__ input_mask,
                 const float* __restrict__ t0p,
                 const float* __restrict__ t1p,
                 const float* __restrict__ mup,
                 const float* __restrict__ betap,
                 float* __restrict__ out)
{
    const int lane = threadIdx.x & 31;
    const int wid  = threadIdx.x >> 5;
    const int row  = blockIdx.x * WPB + wid;

    const float mu   = log1pf(expf(__ldg(mup)));
    const float beta = log1pf(expf(__ldg(betap)));
    const float t0   = __ldg(t0p);
    const float t1   = __ldg(t1p);

    const size_t rbase = (size_t)row * T_LEN;
    const float4* ev = reinterpret_cast<const float4*>(event_times + rbase);
    const float4* mk = reinterpret_cast<const float4*>(input_mask  + rbase);

    float sumt = 0.f;     // sum mask * t
    float sumidx = 0.f;   // sum mask * index (integer-valued < 2^24: exact)
    float S = 0.f;        // sum masked exp(mu*t - beta*k)
    float T = 0.f;        // running masked count (warp-uniform)

    // ============ phase 1: scan + exp, until terms underflow ============
    int i = 0;
    for (; i < CHUNKS; i++) {
        const float4 e = ev[lane + 32 * i];
        const float4 m = mk[lane + 32 * i];

        const float cnt = (m.x + m.y) + (m.z + m.w);

        sumt = fmaf(m.x, e.x, sumt);
        sumt = fmaf(m.y, e.y, sumt);
        sumt = fmaf(m.z, e.z, sumt);
        sumt = fmaf(m.w, e.w, sumt);

        const float base = (float)(128 * i + 4 * lane);
        sumidx = fmaf(cnt, base, sumidx);
        sumidx += fmaf(3.f, m.w, fmaf(2.f, m.z, m.y));

        // intra-warp inclusive scan of cnt
        float s = cnt;
        #pragma unroll
        for (int off = 1; off < 32; off <<= 1) {
            const float u = __shfl_up_sync(FULL, s, off);
            if (lane >= off) s += u;
        }

        if (beta * T < 104.f) {   // expf underflow bound
            float k = T + (s - cnt);
            if (m.x > 0.5f) { S += expf(fmaf(mu, e.x, -beta * k)); k += 1.f; }
            if (m.y > 0.5f) { S += expf(fmaf(mu, e.y, -beta * k)); k += 1.f; }
            if (m.z > 0.5f) { S += expf(fmaf(mu, e.z, -beta * k)); k += 1.f; }
            if (m.w > 0.5f) { S += expf(fmaf(mu, e.w, -beta * k)); }
        }
        T += __shfl_sync(FULL, s, 31);

        if (beta * T >= 106.f) { i++; break; }   // all remaining terms == 0.0f
    }

    // ============ phase 2: pure streaming, 2-chunk batched loads ============
    for (; i + 2 <= CHUNKS; i += 2) {
        const float4 e0 = ev[lane + 32 * (i + 0)];
        const float4 e1 = ev[lane + 32 * (i + 1)];
        const float4 m0 = mk[lane + 32 * (i + 0)];
        const float4 m1 = mk[lane + 32 * (i + 1)];

        const float b0 = (float)(128 * (i + 0) + 4 * lane);
        const float b1 = (float)(128 * (i + 1) + 4 * lane);

        sumt = fmaf(m0.x, e0.x, sumt); sumt = fmaf(m0.y, e0.y, sumt);
        sumt = fmaf(m0.z, e0.z, sumt); sumt = fmaf(m0.w, e0.w, sumt);
        sumt = fmaf(m1.x, e1.x, sumt); sumt = fmaf(m1.y, e1.y, sumt);
        sumt = fmaf(m1.z, e1.z, sumt); sumt = fmaf(m1.w, e1.w, sumt);

        const float c0 = (m0.x + m0.y) + (m0.z + m0.w);
        const float c1 = (m1.x + m1.y) + (m1.z + m1.w);

        sumidx = fmaf(c0, b0, sumidx);
        sumidx += fmaf(3.f, m0.w, fmaf(2.f, m0.z, m0.y));
        sumidx = fmaf(c1, b1, sumidx);
        sumidx += fmaf(3.f, m1.w, fmaf(2.f, m1.z, m1.y));
    }
    // tail (0-1 chunk)
    for (; i < CHUNKS; i++) {
        const float4 e = ev[lane + 32 * i];
        const float4 m = mk[lane + 32 * i];
        sumt = fmaf(m.x, e.x, sumt); sumt = fmaf(m.y, e.y, sumt);
        sumt = fmaf(m.z, e.z, sumt); sumt = fmaf(m.w, e.w, sumt);
        const float cnt = (m.x + m.y) + (m.z + m.w);
        const float base = (float)(128 * i + 4 * lane);
        sumidx = fmaf(cnt, base, sumidx);
        sumidx += fmaf(3.f, m.w, fmaf(2.f, m.z, m.y));
    }

    // ============ warp reductions ============
    #pragma unroll
    for (int off = 16; off; off >>= 1) {
        sumt   += __shfl_down_sync(FULL, sumt,   off);
        sumidx += __shfl_down_sync(FULL, sumidx, off);
        S      += __shfl_down_sync(FULL, S,      off);
    }

    if (lane == 0) {
        const float ll  = fmaf(mu, sumt, -beta * sumidx);
        const float emb = expf(-beta);
        // telescoped compensator: (1-e^{-b})*S - e^{mu*t0} + e^{mu*t1 - b*M}
        float comp = fmaf(1.f - emb, S, -expf(mu * t0));
        comp += expf(fmaf(mu, t1, -beta * T));   // exact 0 after underflow
        out[row] = ll - comp / mu;
    }
}

extern "C" void kernel_launch(void* const* d_in, const int* in_sizes, int n_in,
                              void* d_out, int out_size)
{
    const float* event_times = (const float*)d_in[0];
    // d_in[1] = spatial_locations : unused by the op
    const float* input_mask  = (const float*)d_in[2];
    const float* t0          = (const float*)d_in[3];
    const float* t1          = (const float*)d_in[4];
    const float* mu_param    = (const float*)d_in[5];
    const float* beta_param  = (const float*)d_in[6];
    float* out = (float*)d_out;

    const int n_rows = out_size;  // 8192
    scpp_kernel<<<n_rows / WPB, 256>>>(event_times, input_mask,
                                       t0, t1, mu_param, beta_param, out);
}

// round 9
// speedup vs baseline: 1.1737x; 1.1737x over previous
#include <cuda_runtime.h>
#include <math.h>

#define FULL 0xFFFFFFFFu
#define T_LEN 2048
#define CHUNKS 16          // 16 chunks x 128 elems = 2048
#define WPB 8              // warps per block

// streaming sums for one chunk (e,m known, chunk index i)
#define SUMS(e, m, i)                                                     \
    do {                                                                  \
        sumt = fmaf((m).x, (e).x, sumt); sumt = fmaf((m).y, (e).y, sumt); \
        sumt = fmaf((m).z, (e).z, sumt); sumt = fmaf((m).w, (e).w, sumt); \
        const float cnt_ = ((m).x + (m).y) + ((m).z + (m).w);             \
        const float base_ = (float)(128 * (i) + 4 * lane);                \
        sumidx = fmaf(cnt_, base_, sumidx);                               \
        sumidx += fmaf(3.f, (m).w, fmaf(2.f, (m).z, (m).y));              \
    } while (0)

__global__ __launch_bounds__(256, 4)
void scpp_kernel(const float* __restrict__ event_times,
                 const float* __restrict__ input_mask,
                 const float* __restrict__ t0p,
                 const float* __restrict__ t1p,
                 const float* __restrict__ mup,
                 const float* __restrict__ betap,
                 float* __restrict__ out)
{
    const int lane = threadIdx.x & 31;
    const int wid  = threadIdx.x >> 5;
    const int row  = blockIdx.x * WPB + wid;

    const float mu   = log1pf(expf(__ldg(mup)));
    const float beta = log1pf(expf(__ldg(betap)));
    const float t0   = __ldg(t0p);
    const float t1   = __ldg(t1p);

    const size_t rbase = (size_t)row * T_LEN;
    const float4* ev = reinterpret_cast<const float4*>(event_times + rbase);
    const float4* mk = reinterpret_cast<const float4*>(input_mask  + rbase);

    // ---- front-batched loads: chunks 0,1 (phase 1) + chunks 2..5 prefetch ----
    const float4 a0e = ev[lane +  0], a1e = ev[lane + 32];
    const float4 a0m = mk[lane +  0], a1m = mk[lane + 32];
    float4 p0e = ev[lane + 32*2], p1e = ev[lane + 32*3];
    float4 p2e = ev[lane + 32*4], p3e = ev[lane + 32*5];
    float4 p0m = mk[lane + 32*2], p1m = mk[lane + 32*3];
    float4 p2m = mk[lane + 32*4], p3m = mk[lane + 32*5];

    float sumt = 0.f;     // sum mask * t
    float sumidx = 0.f;   // sum mask * index (integer-valued < 2^24: exact)
    float S = 0.f;        // sum masked exp(mu*t - beta*k)
    float T = 0.f;        // running masked count (warp-uniform)

    // ============ phase 1: chunks 0,1 scan + gated exp (loads 2-5 in flight) ====
    #pragma unroll
    for (int i = 0; i < 2; i++) {
        const float4 e = (i == 0) ? a0e : a1e;
        const float4 m = (i == 0) ? a0m : a1m;

        SUMS(e, m, i);
        const float cnt = (m.x + m.y) + (m.z + m.w);

        float s = cnt;
        #pragma unroll
        for (int off = 1; off < 32; off <<= 1) {
            const float u = __shfl_up_sync(FULL, s, off);
            if (lane >= off) s += u;
        }

        if (beta * T < 104.f) {   // expf underflow bound
            float k = T + (s - cnt);
            if (m.x > 0.5f) { S += expf(fmaf(mu, e.x, -beta * k)); k += 1.f; }
            if (m.y > 0.5f) { S += expf(fmaf(mu, e.y, -beta * k)); k += 1.f; }
            if (m.z > 0.5f) { S += expf(fmaf(mu, e.z, -beta * k)); k += 1.f; }
            if (m.w > 0.5f) { S += expf(fmaf(mu, e.w, -beta * k)); }
        }
        T += __shfl_sync(FULL, s, 31);
    }

    // rare fallback (correctness for arbitrary masks): scan+exp only, reloads
    if (beta * T < 106.f) {
        for (int i = 2; i < CHUNKS; i++) {
            const float4 e = ev[lane + 32 * i];
            const float4 m = mk[lane + 32 * i];
            const float cnt = (m.x + m.y) + (m.z + m.w);
            float s = cnt;
            #pragma unroll
            for (int off = 1; off < 32; off <<= 1) {
                const float u = __shfl_up_sync(FULL, s, off);
                if (lane >= off) s += u;
            }
            if (beta * T < 104.f) {
                float k = T + (s - cnt);
                if (m.x > 0.5f) { S += expf(fmaf(mu, e.x, -beta * k)); k += 1.f; }
                if (m.y > 0.5f) { S += expf(fmaf(mu, e.y, -beta * k)); k += 1.f; }
                if (m.z > 0.5f) { S += expf(fmaf(mu, e.z, -beta * k)); k += 1.f; }
                if (m.w > 0.5f) { S += expf(fmaf(mu, e.w, -beta * k)); }
            }
            T += __shfl_sync(FULL, s, 31);
            if (beta * T >= 106.f) break;
        }
    }

    // ============ phase 2: streaming (chunks 2..15), pipelined batches ==========
    // consume 2..5 (already loaded) while 6..9 load
    float4 q0e = ev[lane + 32*6], q1e = ev[lane + 32*7];
    float4 q2e = ev[lane + 32*8], q3e = ev[lane + 32*9];
    float4 q0m = mk[lane + 32*6], q1m = mk[lane + 32*7];
    float4 q2m = mk[lane + 32*8], q3m = mk[lane + 32*9];
    SUMS(p0e, p0m, 2); SUMS(p1e, p1m, 3); SUMS(p2e, p2m, 4); SUMS(p3e, p3m, 5);

    // consume 6..9 while 10..13 load
    p0e = ev[lane + 32*10]; p1e = ev[lane + 32*11];
    p2e = ev[lane + 32*12]; p3e = ev[lane + 32*13];
    p0m = mk[lane + 32*10]; p1m = mk[lane + 32*11];
    p2m = mk[lane + 32*12]; p3m = mk[lane + 32*13];
    SUMS(q0e, q0m, 6); SUMS(q1e, q1m, 7); SUMS(q2e, q2m, 8); SUMS(q3e, q3m, 9);

    // consume 10..13 while 14..15 load
    q0e = ev[lane + 32*14]; q1e = ev[lane + 32*15];
    q0m = mk[lane + 32*14]; q1m = mk[lane + 32*15];
    SUMS(p0e, p0m, 10); SUMS(p1e, p1m, 11); SUMS(p2e, p2m, 12); SUMS(p3e, p3m, 13);

    SUMS(q0e, q0m, 14); SUMS(q1e, q1m, 15);

    // ============ warp reductions ============
    #pragma unroll
    for (int off = 16; off; off >>= 1) {
        sumt   += __shfl_down_sync(FULL, sumt,   off);
        sumidx += __shfl_down_sync(FULL, sumidx, off);
        S      += __shfl_down_sync(FULL, S,      off);
    }

    if (lane == 0) {
        const float ll  = fmaf(mu, sumt, -beta * sumidx);
        const float emb = expf(-beta);
        // telescoped compensator: (1-e^{-b})*S - e^{mu*t0} + e^{mu*t1 - b*M}
        float comp = fmaf(1.f - emb, S, -expf(mu * t0));
        comp += expf(fmaf(mu, t1, -beta * T));   // exact 0 after underflow
        out[row] = ll - comp / mu;
    }
}

extern "C" void kernel_launch(void* const* d_in, const int* in_sizes, int n_in,
                              void* d_out, int out_size)
{
    const float* event_times = (const float*)d_in[0];
    // d_in[1] = spatial_locations : unused by the op
    const float* input_mask  = (const float*)d_in[2];
    const float* t0          = (const float*)d_in[3];
    const float* t1          = (const float*)d_in[4];
    const float* mu_param    = (const float*)d_in[5];
    const float* beta_param  = (const float*)d_in[6];
    float* out = (float*)d_out;

    const int n_rows = out_size;  // 8192
    scpp_kernel<<<n_rows / WPB, 256>>>(event_times, input_mask,
                                       t0, t1, mu_param, beta_param, out);
}